// round 10
// baseline (speedup 1.0000x reference)
#include <cuda_runtime.h>
#include <cuda_fp16.h>
#include <math.h>
#include <stdint.h>

// ---------------- problem constants ----------------
#define TT 4096
#define HH 2048
#define EE 32
#define II 1024
#define TOPK 8
#define NGROUP 8
#define GSIZE 4
#define TOPKG 4
#define SSI 2048
#define RSCALE 2.5f

// ---------------- scratch (device globals) ----------------
__device__ float g_cw[(size_t)TT * EE];
__device__ int   g_tok[(size_t)EE * TT];
__device__ int   g_cnt[EE];
__device__ int   g_slot[(size_t)EE * TT];     // inverse map: slot of token t in expert e
__device__ int   g_tids[(size_t)TT * TOPK];   // per-token expert ids (router order)
__device__ float g_tw  [(size_t)TT * TOPK];   // per-token normalized weights

__device__ __half s_hs  [(size_t)TT * HH];
__device__ __half s_wgu [(size_t)EE * HH * 2 * II];   // [e][k=H][n'=2I] gate/up interleaved
__device__ __half s_wdn [(size_t)EE * II * HH];       // [e][k=I][n=H]
__device__ __half s_sgu [(size_t)HH * 2 * SSI];       // [k=H][n'=2SI] interleaved
__device__ __half s_sdn [(size_t)SSI * HH];           // [k=SI][n=H]

__device__ __half g_ha [(size_t)EE * TT * II];
__device__ __half s_hsa[(size_t)TT * SSI];
__device__ float  g_dn [(size_t)EE * TT * HH];        // dense routed-down outputs (1 GB)

// ---------------- router ----------------
__global__ void router_kernel(const float* __restrict__ hs,
                              const float* __restrict__ gw,
                              const float* __restrict__ bias) {
    int t    = blockIdx.x * blockDim.y + threadIdx.y;
    int lane = threadIdx.x;
    const float* hrow = hs + (size_t)t * HH;
    float acc = 0.f;
    for (int h = 0; h < HH; h += 4) {
        float4 hv = *(const float4*)(hrow + h);
        acc += hv.x * gw[(h + 0) * EE + lane];
        acc += hv.y * gw[(h + 1) * EE + lane];
        acc += hv.z * gw[(h + 2) * EE + lane];
        acc += hv.w * gw[(h + 3) * EE + lane];
    }
    float score = 1.f / (1.f + expf(-acc));
    float sc    = score + bias[lane];
    __shared__ float s_score[8][32];
    __shared__ float s_sc[8][32];
    s_score[threadIdx.y][lane] = score;
    s_sc[threadIdx.y][lane]    = sc;
    __syncwarp();
    if (lane == 0) {
        float scv[EE], scoresv[EE];
        for (int e = 0; e < EE; e++) { scv[e] = s_sc[threadIdx.y][e]; scoresv[e] = s_score[threadIdx.y][e]; }
        float gs[NGROUP];
        for (int g = 0; g < NGROUP; g++) {
            float m1 = -INFINITY; int i1 = 0;
            for (int j = 0; j < GSIZE; j++) {
                float v = scv[g * GSIZE + j];
                if (v > m1) { m1 = v; i1 = j; }
            }
            float m2 = -INFINITY;
            for (int j = 0; j < GSIZE; j++)
                if (j != i1) { float v = scv[g * GSIZE + j]; if (v > m2) m2 = v; }
            gs[g] = m1 + m2;
        }
        bool gsel[NGROUP];
        for (int g = 0; g < NGROUP; g++) gsel[g] = false;
        for (int it = 0; it < TOPKG; it++) {
            float best = -INFINITY; int bi = 0;
            for (int g = 0; g < NGROUP; g++)
                if (!gsel[g] && gs[g] > best) { best = gs[g]; bi = g; }
            gsel[bi] = true;
        }
        float masked[EE];
        for (int e = 0; e < EE; e++) masked[e] = gsel[e / GSIZE] ? scv[e] : -INFINITY;
        int ids[TOPK]; float wv[TOPK]; float wsum = 0.f;
        for (int k = 0; k < TOPK; k++) {
            float best = -INFINITY; int bi = 0;
            for (int e = 0; e < EE; e++)
                if (masked[e] > best) { best = masked[e]; bi = e; }
            masked[bi] = -INFINITY;
            ids[k] = bi; wv[k] = scoresv[bi]; wsum += wv[k];
        }
        float inv = 1.f / (wsum + 1e-20f);
        float row[EE];
        for (int e = 0; e < EE; e++) row[e] = 0.f;
        for (int k = 0; k < TOPK; k++) {
            row[ids[k]] = wv[k] * inv;
            g_tids[(size_t)t * TOPK + k] = ids[k];
            g_tw[(size_t)t * TOPK + k]   = wv[k] * inv;
        }
        for (int e = 0; e < EE; e++) g_cw[(size_t)t * EE + e] = row[e];
    }
}

__global__ void gather_kernel() {
    int e = blockIdx.x;
    int lane = threadIdx.x;
    int cnt = 0;
    for (int base = 0; base < TT; base += 32) {
        int t = base + lane;
        bool sel = g_cw[(size_t)t * EE + e] > 0.f;
        unsigned m = __ballot_sync(0xffffffffu, sel);
        int pos = cnt + __popc(m & ((1u << lane) - 1u));
        if (sel) {
            g_tok[(size_t)e * TT + pos] = t;
            g_slot[(size_t)e * TT + t]  = pos;
        }
        cnt += __popc(m);
    }
    if (lane == 0) g_cnt[e] = cnt;
}

// ---------------- fp32 -> fp16 plain convert (coalesced 16B stores) ----------------
__global__ void conv_kernel(const float* __restrict__ src, __half* __restrict__ dst, size_t n) {
    size_t i = ((size_t)blockIdx.x * blockDim.x + threadIdx.x) * 8;
    if (i >= n) return;
    float4 v0 = *(const float4*)(src + i);
    float4 v1 = *(const float4*)(src + i + 4);
    __half hv[8] = {__float2half_rn(v0.x), __float2half_rn(v0.y),
                    __float2half_rn(v0.z), __float2half_rn(v0.w),
                    __float2half_rn(v1.x), __float2half_rn(v1.y),
                    __float2half_rn(v1.z), __float2half_rn(v1.w)};
    *(uint4*)(dst + i) = *(uint4*)hv;
}

// ---------------- fp32 -> fp16 with gate/up interleave, coalesced writes ----------------
__global__ void conv_ilv_kernel(const float* __restrict__ src, __half* __restrict__ dst,
                                int half, size_t sE, size_t dE) {
    int e = blockIdx.z;
    int row = blockIdx.y;
    int n = (blockIdx.x * blockDim.x + threadIdx.x) * 4;   // gate index
    const float* S = src + (size_t)e * sE + (size_t)row * (2 * half);
    __half* D = dst + (size_t)e * dE + (size_t)row * (2 * half);
    float4 g = *(const float4*)(S + n);
    float4 u = *(const float4*)(S + half + n);
    __half hv[8] = {__float2half_rn(g.x), __float2half_rn(u.x),
                    __float2half_rn(g.y), __float2half_rn(u.y),
                    __float2half_rn(g.z), __float2half_rn(u.z),
                    __float2half_rn(g.w), __float2half_rn(u.w)};
    *(uint4*)(D + 2 * n) = *(uint4*)hv;
}

// ---------------- final combine: out[t] += RSCALE * sum_k w_k * g_dn[e_k][slot] ----------------
__global__ void combine_kernel(float* __restrict__ out) {
    int t = blockIdx.y;
    int h = (blockIdx.x * blockDim.x + threadIdx.x) * 4;
    int   eids[TOPK];
    float ws[TOPK];
    const float* dnrow[TOPK];
#pragma unroll
    for (int k = 0; k < TOPK; k++) {
        int e = g_tids[(size_t)t * TOPK + k];
        eids[k] = e;
        ws[k] = RSCALE * g_tw[(size_t)t * TOPK + k];
        int s = g_slot[(size_t)e * TT + t];
        dnrow[k] = g_dn + ((size_t)e * TT + s) * HH;
    }
    float4 o = *(float4*)(out + (size_t)t * HH + h);
#pragma unroll
    for (int k = 0; k < TOPK; k++) {
        float4 v = *(const float4*)(dnrow[k] + h);
        o.x += ws[k] * v.x;
        o.y += ws[k] * v.y;
        o.z += ws[k] * v.z;
        o.w += ws[k] * v.w;
    }
    *(float4*)(out + (size_t)t * HH + h) = o;
}

// ---------------- mma.sync fp16 GEMM, 128x128 CTA tile, 3-stage pipeline ----------------
#define PA 72          // A smem row pitch (elems), BK=64 + 8 pad
#define PB 136         // B smem row pitch (elems), 128 cols + 8 pad
#define BK 64
#define ASZB (128 * PA * 2)        // 18432
#define BSZB (BK * PB * 2)         // 17408
#define STAGE_B (ASZB + BSZB)      // 35840
#define NSTAGE 3
#define SMEM_BYTES (NSTAGE * STAGE_B)   // 107520

__device__ __forceinline__ void cp16(uint32_t dst, const void* src, int sz) {
    asm volatile("cp.async.cg.shared.global [%0], [%1], 16, %2;\n"
                 :: "r"(dst), "l"(src), "r"(sz));
}
__device__ __forceinline__ void cpcommit() { asm volatile("cp.async.commit_group;\n"); }
template<int N> __device__ __forceinline__ void cpwait() {
    asm volatile("cp.async.wait_group %0;\n" :: "n"(N));
}
__device__ __forceinline__ void ldsm4(uint32_t* r, uint32_t addr) {
    asm volatile("ldmatrix.sync.aligned.m8n8.x4.shared.b16 {%0,%1,%2,%3}, [%4];"
                 : "=r"(r[0]), "=r"(r[1]), "=r"(r[2]), "=r"(r[3]) : "r"(addr));
}
__device__ __forceinline__ void ldsm4t(uint32_t* r, uint32_t addr) {
    asm volatile("ldmatrix.sync.aligned.m8n8.x4.trans.shared.b16 {%0,%1,%2,%3}, [%4];"
                 : "=r"(r[0]), "=r"(r[1]), "=r"(r[2]), "=r"(r[3]) : "r"(addr));
}
__device__ __forceinline__ void mmaf16(float* c, const uint32_t* a, uint32_t b0, uint32_t b1) {
    asm volatile("mma.sync.aligned.m16n8k16.row.col.f32.f16.f16.f32 "
                 "{%0,%1,%2,%3}, {%4,%5,%6,%7}, {%8,%9}, {%0,%1,%2,%3};"
                 : "+f"(c[0]), "+f"(c[1]), "+f"(c[2]), "+f"(c[3])
                 : "r"(a[0]), "r"(a[1]), "r"(a[2]), "r"(a[3]), "r"(b0), "r"(b1));
}

// GA: gather A rows by token list.
// EPI: 0 plain fp32 store (with expert stride); 1 silu(gate)*up -> fp16 (interleaved cols)
template<bool GA, int EPI>
__global__ __launch_bounds__(256, 2)
void hgemm(const __half* __restrict__ A, size_t sAe, int lda,
           const __half* __restrict__ B, size_t sBe, int ldb,
           float* __restrict__ C, size_t sCe, int ldc,
           __half* __restrict__ D, size_t sDe, int ldd,
           int Mdir, const int* __restrict__ cntp, int K,
           const int* __restrict__ tokall)
{
    extern __shared__ char smraw[];
    int z = blockIdx.z;
    int M = cntp ? cntp[z] : Mdir;
    int row0 = blockIdx.y * 128;
    if (row0 >= M) return;
    int col0 = blockIdx.x * 128;

    const __half* Az = A + (size_t)z * sAe;
    const __half* Bz = B + (size_t)z * sBe;
    const int* tokz = GA ? tokall + (size_t)z * TT : nullptr;

    int tid = threadIdx.x;
    uint32_t sb = (uint32_t)__cvta_generic_to_shared(smraw);

    long aRow[4];
    int r0t = tid >> 3;
    int segA = (tid & 7) * 8;
#pragma unroll
    for (int it = 0; it < 4; it++) {
        int grow = row0 + r0t + 32 * it;
        if (grow < M) aRow[it] = GA ? (long)tokz[grow] : (long)grow;
        else          aRow[it] = -1;
    }

    auto load_stage = [&](int kt, int s) {
        uint32_t base = sb + (uint32_t)s * STAGE_B;
#pragma unroll
        for (int it = 0; it < 4; it++) {
            int r = r0t + 32 * it;
            uint32_t d = base + (uint32_t)(r * PA + segA) * 2;
            long src = aRow[it];
            const __half* pa = (src >= 0) ? Az + (size_t)src * lda + kt * BK + segA : Az;
            cp16(d, pa, (src >= 0) ? 16 : 0);
        }
#pragma unroll
        for (int it = 0; it < 4; it++) {
            int q = tid + it * 256;
            int kr = q >> 4;
            int ns = (q & 15) * 8;
            uint32_t d = base + ASZB + (uint32_t)(kr * PB + ns) * 2;
            cp16(d, Bz + (size_t)(kt * BK + kr) * ldb + col0 + ns, 16);
        }
        cpcommit();
    };

    int lane = tid & 31, wid = tid >> 5;
    int wm = wid & 3, wn = wid >> 2;   // 4 warps M (32 rows), 2 warps N (64 cols)

    float acc[2][8][4];
#pragma unroll
    for (int a = 0; a < 2; a++)
#pragma unroll
        for (int b = 0; b < 8; b++)
#pragma unroll
            for (int c = 0; c < 4; c++) acc[a][b][c] = 0.f;

    int NT = K / BK;
    load_stage(0, 0);
    if (NT > 1) load_stage(1, 1);
    for (int kt = 0; kt < NT; kt++) {
        int s = kt % NSTAGE;
        if (kt + 2 < NT) { load_stage(kt + 2, (kt + 2) % NSTAGE); cpwait<2>(); }
        else if (kt + 1 < NT) { cpwait<1>(); }
        else { cpwait<0>(); }
        __syncthreads();
        uint32_t base = sb + (uint32_t)s * STAGE_B;
        int arow = lane & 15;
        int achk = lane >> 4;
#pragma unroll
        for (int s2 = 0; s2 < 4; s2++) {
            int k0 = s2 * 16;
            uint32_t a_r[2][4];
#pragma unroll
            for (int mt = 0; mt < 2; mt++) {
                uint32_t off = (uint32_t)((wm * 32 + mt * 16 + arow) * PA + k0 + achk * 8) * 2;
                ldsm4(a_r[mt], base + off);
            }
#pragma unroll
            for (int nt = 0; nt < 4; nt++) {
                uint32_t boff = (uint32_t)((k0 + arow) * PB + wn * 64 + nt * 16 + achk * 8) * 2;
                uint32_t bfr[4];
                ldsm4t(bfr, base + ASZB + boff);
#pragma unroll
                for (int mt = 0; mt < 2; mt++) {
#pragma unroll
                    for (int j = 0; j < 2; j++)
                        mmaf16(acc[mt][nt * 2 + j], a_r[mt], bfr[2 * j], bfr[2 * j + 1]);
                }
            }
        }
        __syncthreads();
    }

    // ---------------- epilogue ----------------
    int r_base = row0 + wm * 32 + (lane >> 2);
    int c_base = col0 + wn * 64 + (lane & 3) * 2;
#pragma unroll
    for (int mt = 0; mt < 2; mt++) {
#pragma unroll
        for (int half = 0; half < 2; half++) {
            int r = r_base + mt * 16 + half * 8;
            if (r >= M) continue;
            if (EPI == 0) {
                float* Crow = C + (size_t)z * sCe + (size_t)r * ldc;
#pragma unroll
                for (int q = 0; q < 8; q++) {
                    int c = c_base + q * 8;
                    float2 v = make_float2(acc[mt][q][half * 2 + 0], acc[mt][q][half * 2 + 1]);
                    *(float2*)&Crow[c] = v;
                }
            } else {  // EPI == 1: even col = gate, odd col = up
                int cb2 = (c_base >> 1);
                __half* DR = D + (size_t)z * sDe + (size_t)r * ldd;
#pragma unroll
                for (int q = 0; q < 8; q++) {
                    float g = acc[mt][q][half * 2 + 0];
                    float u = acc[mt][q][half * 2 + 1];
                    float h = u * (g / (1.f + expf(-g)));
                    DR[cb2 + q * 4] = __float2half_rn(h);
                }
            }
        }
    }
}

// ---------------- launcher ----------------
extern "C" void kernel_launch(void* const* d_in, const int* in_sizes, int n_in,
                              void* d_out, int out_size) {
    const float* hs  = (const float*)d_in[0];
    const float* gw  = (const float*)d_in[1];
    const float* gb  = (const float*)d_in[2];
    const float* wgu = (const float*)d_in[3];  // [E,H,2I]
    const float* wdn = (const float*)d_in[4];  // [E,I,H]
    const float* sgu = (const float*)d_in[5];  // [H,2SI]
    const float* sdn = (const float*)d_in[6];  // [SI,H]
    float* out = (float*)d_out;

    cudaFuncSetAttribute((const void*)hgemm<false, 0>, cudaFuncAttributeMaxDynamicSharedMemorySize, SMEM_BYTES);
    cudaFuncSetAttribute((const void*)hgemm<false, 1>, cudaFuncAttributeMaxDynamicSharedMemorySize, SMEM_BYTES);
    cudaFuncSetAttribute((const void*)hgemm<true,  1>, cudaFuncAttributeMaxDynamicSharedMemorySize, SMEM_BYTES);

    __half *p_hs, *p_wgu, *p_wdn, *p_sgu, *p_sdn, *p_ha, *p_hsa;
    float *p_dn;
    int *p_tok, *p_cnt;
    cudaGetSymbolAddress((void**)&p_hs,  s_hs);
    cudaGetSymbolAddress((void**)&p_wgu, s_wgu);
    cudaGetSymbolAddress((void**)&p_wdn, s_wdn);
    cudaGetSymbolAddress((void**)&p_sgu, s_sgu);
    cudaGetSymbolAddress((void**)&p_sdn, s_sdn);
    cudaGetSymbolAddress((void**)&p_ha,  g_ha);
    cudaGetSymbolAddress((void**)&p_hsa, s_hsa);
    cudaGetSymbolAddress((void**)&p_dn,  g_dn);
    cudaGetSymbolAddress((void**)&p_tok, g_tok);
    cudaGetSymbolAddress((void**)&p_cnt, g_cnt);

    // 0. conversions
    conv_kernel<<<(unsigned)((size_t)TT * HH / 8 / 256), 256>>>(hs, p_hs, (size_t)TT * HH);
    conv_ilv_kernel<<<dim3(II / (4 * 256), HH, EE), 256>>>(
        wgu, p_wgu, II, (size_t)HH * 2 * II, (size_t)HH * 2 * II);
    conv_kernel<<<(unsigned)((size_t)EE * II * HH / 8 / 256), 256>>>(wdn, p_wdn, (size_t)EE * II * HH);
    conv_ilv_kernel<<<dim3(SSI / (4 * 256), HH, 1), 256>>>(
        sgu, p_sgu, SSI, 0, 0);
    conv_kernel<<<(unsigned)((size_t)SSI * HH / 8 / 256), 256>>>(sdn, p_sdn, (size_t)SSI * HH);

    // 1. router + compaction
    router_kernel<<<TT / 8, dim3(32, 8)>>>(hs, gw, gb);
    gather_kernel<<<EE, 32>>>();

    // 2. shared gate_up (interleaved N=2*SSI) -> fused silu -> s_hsa
    hgemm<false, 1><<<dim3((2 * SSI) / 128, TT / 128, 1), 256, SMEM_BYTES>>>(
        p_hs, 0, HH,
        p_sgu, 0, 2 * SSI,
        nullptr, 0, 0,
        p_hsa, 0, SSI,
        TT, nullptr, HH, nullptr);

    // 3. shared down -> out (plain store, overwrites poison)
    hgemm<false, 0><<<dim3(HH / 128, TT / 128, 1), 256, SMEM_BYTES>>>(
        p_hsa, 0, SSI,
        p_sdn, 0, HH,
        out, 0, HH,
        nullptr, 0, 0,
        TT, nullptr, SSI, nullptr);

    // 4. routed gate_up (gather rows, interleaved N=2I) -> fused silu -> g_ha
    hgemm<true, 1><<<dim3((2 * II) / 128, TT / 128, EE), 256, SMEM_BYTES>>>(
        p_hs, 0, HH,
        p_wgu, (size_t)HH * 2 * II, 2 * II,
        nullptr, 0, 0,
        p_ha, (size_t)TT * II, II,
        0, p_cnt, HH, p_tok);

    // 5. routed down -> dense g_dn (plain stores, no atomics)
    hgemm<false, 0><<<dim3(HH / 128, TT / 128, EE), 256, SMEM_BYTES>>>(
        p_ha, (size_t)TT * II, II,
        p_wdn, (size_t)II * HH, HH,
        p_dn, (size_t)TT * HH, HH,
        nullptr, 0, 0,
        0, p_cnt, II, p_tok);

    // 6. weighted gather-combine into out
    combine_kernel<<<dim3(HH / (4 * 256), TT), 256>>>(out);
}

// round 12
// speedup vs baseline: 1.0681x; 1.0681x over previous
#include <cuda_runtime.h>
#include <cuda_fp16.h>
#include <math.h>
#include <stdint.h>

// ---------------- problem constants ----------------
#define TT 4096
#define HH 2048
#define EE 32
#define II 1024
#define TOPK 8
#define NGROUP 8
#define GSIZE 4
#define TOPKG 4
#define SSI 2048
#define RSCALE 2.5f

// ---------------- scratch (device globals) ----------------
__device__ float g_cw[(size_t)TT * EE];
__device__ int   g_tok[(size_t)EE * TT];
__device__ int   g_cnt[EE];

__device__ __half s_hs  [(size_t)TT * HH];
__device__ __half s_wgu [(size_t)EE * HH * 2 * II];   // [e][k=H][n'=2I] gate/up interleaved
__device__ __half s_wdn [(size_t)EE * II * HH];       // [e][k=I][n=H]
__device__ __half s_sgu [(size_t)HH * 2 * SSI];       // [k=H][n'=2SI] interleaved
__device__ __half s_sdn [(size_t)SSI * HH];           // [k=SI][n=H]

__device__ __half g_ha [(size_t)EE * TT * II];
__device__ __half s_hsa[(size_t)TT * SSI];

// ---------------- router ----------------
__global__ void router_kernel(const float* __restrict__ hs,
                              const float* __restrict__ gw,
                              const float* __restrict__ bias) {
    int t    = blockIdx.x * blockDim.y + threadIdx.y;
    int lane = threadIdx.x;
    const float* hrow = hs + (size_t)t * HH;
    float acc = 0.f;
    for (int h = 0; h < HH; h += 4) {
        float4 hv = *(const float4*)(hrow + h);
        acc += hv.x * gw[(h + 0) * EE + lane];
        acc += hv.y * gw[(h + 1) * EE + lane];
        acc += hv.z * gw[(h + 2) * EE + lane];
        acc += hv.w * gw[(h + 3) * EE + lane];
    }
    float score = 1.f / (1.f + expf(-acc));
    float sc    = score + bias[lane];
    __shared__ float s_score[8][32];
    __shared__ float s_sc[8][32];
    s_score[threadIdx.y][lane] = score;
    s_sc[threadIdx.y][lane]    = sc;
    __syncwarp();
    if (lane == 0) {
        float scv[EE], scoresv[EE];
        for (int e = 0; e < EE; e++) { scv[e] = s_sc[threadIdx.y][e]; scoresv[e] = s_score[threadIdx.y][e]; }
        float gs[NGROUP];
        for (int g = 0; g < NGROUP; g++) {
            float m1 = -INFINITY; int i1 = 0;
            for (int j = 0; j < GSIZE; j++) {
                float v = scv[g * GSIZE + j];
                if (v > m1) { m1 = v; i1 = j; }
            }
            float m2 = -INFINITY;
            for (int j = 0; j < GSIZE; j++)
                if (j != i1) { float v = scv[g * GSIZE + j]; if (v > m2) m2 = v; }
            gs[g] = m1 + m2;
        }
        bool gsel[NGROUP];
        for (int g = 0; g < NGROUP; g++) gsel[g] = false;
        for (int it = 0; it < TOPKG; it++) {
            float best = -INFINITY; int bi = 0;
            for (int g = 0; g < NGROUP; g++)
                if (!gsel[g] && gs[g] > best) { best = gs[g]; bi = g; }
            gsel[bi] = true;
        }
        float masked[EE];
        for (int e = 0; e < EE; e++) masked[e] = gsel[e / GSIZE] ? scv[e] : -INFINITY;
        int ids[TOPK]; float wv[TOPK]; float wsum = 0.f;
        for (int k = 0; k < TOPK; k++) {
            float best = -INFINITY; int bi = 0;
            for (int e = 0; e < EE; e++)
                if (masked[e] > best) { best = masked[e]; bi = e; }
            masked[bi] = -INFINITY;
            ids[k] = bi; wv[k] = scoresv[bi]; wsum += wv[k];
        }
        float inv = 1.f / (wsum + 1e-20f);
        float row[EE];
        for (int e = 0; e < EE; e++) row[e] = 0.f;
        for (int k = 0; k < TOPK; k++) row[ids[k]] = wv[k] * inv;
        for (int e = 0; e < EE; e++) g_cw[(size_t)t * EE + e] = row[e];
    }
}

__global__ void gather_kernel() {
    int e = blockIdx.x;
    int lane = threadIdx.x;
    int cnt = 0;
    for (int base = 0; base < TT; base += 32) {
        int t = base + lane;
        bool sel = g_cw[(size_t)t * EE + e] > 0.f;
        unsigned m = __ballot_sync(0xffffffffu, sel);
        int pos = cnt + __popc(m & ((1u << lane) - 1u));
        if (sel) g_tok[(size_t)e * TT + pos] = t;
        cnt += __popc(m);
    }
    if (lane == 0) g_cnt[e] = cnt;
}

// ---------------- fp32 -> fp16 plain convert (16 elems/thread, MLP=4) ----------------
__global__ void conv_kernel(const float* __restrict__ src, __half* __restrict__ dst, size_t n) {
    size_t i = ((size_t)blockIdx.x * blockDim.x + threadIdx.x) * 16;
    if (i >= n) return;
    float4 v0 = *(const float4*)(src + i);
    float4 v1 = *(const float4*)(src + i + 4);
    float4 v2 = *(const float4*)(src + i + 8);
    float4 v3 = *(const float4*)(src + i + 12);
    __half h0[8] = {__float2half_rn(v0.x), __float2half_rn(v0.y),
                    __float2half_rn(v0.z), __float2half_rn(v0.w),
                    __float2half_rn(v1.x), __float2half_rn(v1.y),
                    __float2half_rn(v1.z), __float2half_rn(v1.w)};
    __half h1[8] = {__float2half_rn(v2.x), __float2half_rn(v2.y),
                    __float2half_rn(v2.z), __float2half_rn(v2.w),
                    __float2half_rn(v3.x), __float2half_rn(v3.y),
                    __float2half_rn(v3.z), __float2half_rn(v3.w)};
    *(uint4*)(dst + i)     = *(uint4*)h0;
    *(uint4*)(dst + i + 8) = *(uint4*)h1;
}

// ---------------- fp32 -> fp16 gate/up interleave (8 pairs/thread, MLP=4) ----------------
// src row: [gate(0..half-1) | up(half..2*half-1)]; dst row: g0,u0,g1,u1,...
__global__ void conv_ilv_kernel(const float* __restrict__ src, __half* __restrict__ dst,
                                int half, size_t sE, size_t dE) {
    int e = blockIdx.z;
    int row = blockIdx.y;
    int n = (blockIdx.x * blockDim.x + threadIdx.x) * 8;   // gate index
    const float* S = src + (size_t)e * sE + (size_t)row * (2 * half);
    __half* D = dst + (size_t)e * dE + (size_t)row * (2 * half);
    float4 g0 = *(const float4*)(S + n);
    float4 g1 = *(const float4*)(S + n + 4);
    float4 u0 = *(const float4*)(S + half + n);
    float4 u1 = *(const float4*)(S + half + n + 4);
    __half h0[8] = {__float2half_rn(g0.x), __float2half_rn(u0.x),
                    __float2half_rn(g0.y), __float2half_rn(u0.y),
                    __float2half_rn(g0.z), __float2half_rn(u0.z),
                    __float2half_rn(g0.w), __float2half_rn(u0.w)};
    __half h1[8] = {__float2half_rn(g1.x), __float2half_rn(u1.x),
                    __float2half_rn(g1.y), __float2half_rn(u1.y),
                    __float2half_rn(g1.z), __float2half_rn(u1.z),
                    __float2half_rn(g1.w), __float2half_rn(u1.w)};
    *(uint4*)(D + 2 * n)     = *(uint4*)h0;
    *(uint4*)(D + 2 * n + 8) = *(uint4*)h1;
}

// ---------------- mma.sync fp16 GEMM, 128x128 CTA tile, 3-stage pipeline ----------------
#define PA 72          // A smem row pitch (elems), BK=64 + 8 pad
#define PB 136         // B smem row pitch (elems), 128 cols + 8 pad
#define BK 64
#define ASZB (128 * PA * 2)        // 18432
#define BSZB (BK * PB * 2)         // 17408
#define STAGE_B (ASZB + BSZB)      // 35840
#define NSTAGE 3
#define SMEM_BYTES (NSTAGE * STAGE_B)   // 107520

__device__ __forceinline__ void cp16(uint32_t dst, const void* src, int sz) {
    asm volatile("cp.async.cg.shared.global [%0], [%1], 16, %2;\n"
                 :: "r"(dst), "l"(src), "r"(sz));
}
__device__ __forceinline__ void cpcommit() { asm volatile("cp.async.commit_group;\n"); }
template<int N> __device__ __forceinline__ void cpwait() {
    asm volatile("cp.async.wait_group %0;\n" :: "n"(N));
}
__device__ __forceinline__ void ldsm4(uint32_t* r, uint32_t addr) {
    asm volatile("ldmatrix.sync.aligned.m8n8.x4.shared.b16 {%0,%1,%2,%3}, [%4];"
                 : "=r"(r[0]), "=r"(r[1]), "=r"(r[2]), "=r"(r[3]) : "r"(addr));
}
__device__ __forceinline__ void ldsm4t(uint32_t* r, uint32_t addr) {
    asm volatile("ldmatrix.sync.aligned.m8n8.x4.trans.shared.b16 {%0,%1,%2,%3}, [%4];"
                 : "=r"(r[0]), "=r"(r[1]), "=r"(r[2]), "=r"(r[3]) : "r"(addr));
}
__device__ __forceinline__ void mmaf16(float* c, const uint32_t* a, uint32_t b0, uint32_t b1) {
    asm volatile("mma.sync.aligned.m16n8k16.row.col.f32.f16.f16.f32 "
                 "{%0,%1,%2,%3}, {%4,%5,%6,%7}, {%8,%9}, {%0,%1,%2,%3};"
                 : "+f"(c[0]), "+f"(c[1]), "+f"(c[2]), "+f"(c[3])
                 : "r"(a[0]), "r"(a[1]), "r"(a[2]), "r"(a[3]), "r"(b0), "r"(b1));
}

// GA: gather A rows by token list.
// EPI: 0 plain fp32 store; 1 silu(gate)*up -> fp16 (interleaved cols); 2 weighted atomicAdd scatter
template<bool GA, int EPI>
__global__ __launch_bounds__(256, 2)
void hgemm(const __half* __restrict__ A, size_t sAe, int lda,
           const __half* __restrict__ B, size_t sBe, int ldb,
           float* __restrict__ C, int ldc,
           __half* __restrict__ D, size_t sDe, int ldd,
           int Mdir, const int* __restrict__ cntp, int K,
           const int* __restrict__ tokall,
           const float* __restrict__ cw, float wscale)
{
    extern __shared__ char smraw[];
    int z = blockIdx.z;
    int M = cntp ? cntp[z] : Mdir;
    int row0 = blockIdx.y * 128;
    if (row0 >= M) return;
    int col0 = blockIdx.x * 128;

    const __half* Az = A + (size_t)z * sAe;
    const __half* Bz = B + (size_t)z * sBe;
    const int* tokz = (GA || EPI == 2) ? tokall + (size_t)z * TT : nullptr;

    int tid = threadIdx.x;
    uint32_t sb = (uint32_t)__cvta_generic_to_shared(smraw);

    long aRow[4];
    int r0t = tid >> 3;
    int segA = (tid & 7) * 8;
#pragma unroll
    for (int it = 0; it < 4; it++) {
        int grow = row0 + r0t + 32 * it;
        if (grow < M) aRow[it] = GA ? (long)tokz[grow] : (long)grow;
        else          aRow[it] = -1;
    }

    auto load_stage = [&](int kt, int s) {
        uint32_t base = sb + (uint32_t)s * STAGE_B;
#pragma unroll
        for (int it = 0; it < 4; it++) {
            int r = r0t + 32 * it;
            uint32_t d = base + (uint32_t)(r * PA + segA) * 2;
            long src = aRow[it];
            const __half* pa = (src >= 0) ? Az + (size_t)src * lda + kt * BK + segA : Az;
            cp16(d, pa, (src >= 0) ? 16 : 0);
        }
#pragma unroll
        for (int it = 0; it < 4; it++) {
            int q = tid + it * 256;
            int kr = q >> 4;
            int ns = (q & 15) * 8;
            uint32_t d = base + ASZB + (uint32_t)(kr * PB + ns) * 2;
            cp16(d, Bz + (size_t)(kt * BK + kr) * ldb + col0 + ns, 16);
        }
        cpcommit();
    };

    int lane = tid & 31, wid = tid >> 5;
    int wm = wid & 3, wn = wid >> 2;   // 4 warps M (32 rows), 2 warps N (64 cols)

    float acc[2][8][4];
#pragma unroll
    for (int a = 0; a < 2; a++)
#pragma unroll
        for (int b = 0; b < 8; b++)
#pragma unroll
            for (int c = 0; c < 4; c++) acc[a][b][c] = 0.f;

    int NT = K / BK;
    load_stage(0, 0);
    if (NT > 1) load_stage(1, 1);
    for (int kt = 0; kt < NT; kt++) {
        int s = kt % NSTAGE;
        if (kt + 2 < NT) { load_stage(kt + 2, (kt + 2) % NSTAGE); cpwait<2>(); }
        else if (kt + 1 < NT) { cpwait<1>(); }
        else { cpwait<0>(); }
        __syncthreads();
        uint32_t base = sb + (uint32_t)s * STAGE_B;
        int arow = lane & 15;
        int achk = lane >> 4;
#pragma unroll
        for (int s2 = 0; s2 < 4; s2++) {
            int k0 = s2 * 16;
            uint32_t a_r[2][4];
#pragma unroll
            for (int mt = 0; mt < 2; mt++) {
                uint32_t off = (uint32_t)((wm * 32 + mt * 16 + arow) * PA + k0 + achk * 8) * 2;
                ldsm4(a_r[mt], base + off);
            }
            // B-fragment double buffer: prefetch nt+1 while issuing MMAs of nt
            uint32_t bfr[2][4];
            {
                uint32_t boff0 = (uint32_t)((k0 + arow) * PB + wn * 64 + achk * 8) * 2;
                ldsm4t(bfr[0], base + ASZB + boff0);
            }
#pragma unroll
            for (int nt = 0; nt < 4; nt++) {
                if (nt < 3) {
                    uint32_t boffn = (uint32_t)((k0 + arow) * PB + wn * 64 + (nt + 1) * 16 + achk * 8) * 2;
                    ldsm4t(bfr[(nt + 1) & 1], base + ASZB + boffn);
                }
                uint32_t* bcur = bfr[nt & 1];
#pragma unroll
                for (int mt = 0; mt < 2; mt++) {
#pragma unroll
                    for (int j = 0; j < 2; j++)
                        mmaf16(acc[mt][nt * 2 + j], a_r[mt], bcur[2 * j], bcur[2 * j + 1]);
                }
            }
        }
        __syncthreads();
    }

    // ---------------- epilogue ----------------
    int r_base = row0 + wm * 32 + (lane >> 2);
    int c_base = col0 + wn * 64 + (lane & 3) * 2;
#pragma unroll
    for (int mt = 0; mt < 2; mt++) {
#pragma unroll
        for (int half = 0; half < 2; half++) {
            int r = r_base + mt * 16 + half * 8;
            if (r >= M) continue;
            if (EPI == 0) {
                float* Crow = C + (size_t)r * ldc;
#pragma unroll
                for (int q = 0; q < 8; q++) {
                    int c = c_base + q * 8;
                    float2 v = make_float2(acc[mt][q][half * 2 + 0], acc[mt][q][half * 2 + 1]);
                    *(float2*)&Crow[c] = v;
                }
            } else if (EPI == 1) {
                // even col = gate, odd col = up (interleaved weight cols)
                int cb2 = (c_base >> 1);
                __half* DR = D + (size_t)z * sDe + (size_t)r * ldd;
#pragma unroll
                for (int q = 0; q < 8; q++) {
                    float g = acc[mt][q][half * 2 + 0];
                    float u = acc[mt][q][half * 2 + 1];
                    float h = u * (g / (1.f + expf(-g)));
                    DR[cb2 + q * 4] = __float2half_rn(h);
                }
            } else {  // EPI == 2
                int t = tokz[r];
                float wt = wscale * cw[(size_t)t * EE + z];
                float* Crow = C + (size_t)t * ldc;
#pragma unroll
                for (int q = 0; q < 8; q++) {
                    int c = c_base + q * 8;
                    atomicAdd(&Crow[c],     wt * acc[mt][q][half * 2 + 0]);
                    atomicAdd(&Crow[c + 1], wt * acc[mt][q][half * 2 + 1]);
                }
            }
        }
    }
}

// ---------------- launcher ----------------
extern "C" void kernel_launch(void* const* d_in, const int* in_sizes, int n_in,
                              void* d_out, int out_size) {
    const float* hs  = (const float*)d_in[0];
    const float* gw  = (const float*)d_in[1];
    const float* gb  = (const float*)d_in[2];
    const float* wgu = (const float*)d_in[3];  // [E,H,2I]
    const float* wdn = (const float*)d_in[4];  // [E,I,H]
    const float* sgu = (const float*)d_in[5];  // [H,2SI]
    const float* sdn = (const float*)d_in[6];  // [SI,H]
    float* out = (float*)d_out;

    cudaFuncSetAttribute((const void*)hgemm<false, 0>, cudaFuncAttributeMaxDynamicSharedMemorySize, SMEM_BYTES);
    cudaFuncSetAttribute((const void*)hgemm<false, 1>, cudaFuncAttributeMaxDynamicSharedMemorySize, SMEM_BYTES);
    cudaFuncSetAttribute((const void*)hgemm<true,  1>, cudaFuncAttributeMaxDynamicSharedMemorySize, SMEM_BYTES);
    cudaFuncSetAttribute((const void*)hgemm<false, 2>, cudaFuncAttributeMaxDynamicSharedMemorySize, SMEM_BYTES);

    __half *p_hs, *p_wgu, *p_wdn, *p_sgu, *p_sdn, *p_ha, *p_hsa;
    float *p_cw;
    int *p_tok, *p_cnt;
    cudaGetSymbolAddress((void**)&p_hs,  s_hs);
    cudaGetSymbolAddress((void**)&p_wgu, s_wgu);
    cudaGetSymbolAddress((void**)&p_wdn, s_wdn);
    cudaGetSymbolAddress((void**)&p_sgu, s_sgu);
    cudaGetSymbolAddress((void**)&p_sdn, s_sdn);
    cudaGetSymbolAddress((void**)&p_ha,  g_ha);
    cudaGetSymbolAddress((void**)&p_hsa, s_hsa);
    cudaGetSymbolAddress((void**)&p_cw,  g_cw);
    cudaGetSymbolAddress((void**)&p_tok, g_tok);
    cudaGetSymbolAddress((void**)&p_cnt, g_cnt);

    // 0. conversions (high-MLP)
    conv_kernel<<<(unsigned)((size_t)TT * HH / 16 / 256), 256>>>(hs, p_hs, (size_t)TT * HH);
    conv_ilv_kernel<<<dim3(II / (8 * 128), HH, EE), 128>>>(
        wgu, p_wgu, II, (size_t)HH * 2 * II, (size_t)HH * 2 * II);
    conv_kernel<<<(unsigned)((size_t)EE * II * HH / 16 / 256), 256>>>(wdn, p_wdn, (size_t)EE * II * HH);
    conv_ilv_kernel<<<dim3(SSI / (8 * 128), HH, 1), 128>>>(
        sgu, p_sgu, SSI, 0, 0);
    conv_kernel<<<(unsigned)((size_t)SSI * HH / 16 / 256), 256>>>(sdn, p_sdn, (size_t)SSI * HH);

    // 1. router + compaction
    router_kernel<<<TT / 8, dim3(32, 8)>>>(hs, gw, gb);
    gather_kernel<<<EE, 32>>>();

    // 2. shared gate_up (interleaved N=2*SSI) -> fused silu -> s_hsa
    hgemm<false, 1><<<dim3((2 * SSI) / 128, TT / 128, 1), 256, SMEM_BYTES>>>(
        p_hs, 0, HH,
        p_sgu, 0, 2 * SSI,
        nullptr, 0,
        p_hsa, 0, SSI,
        TT, nullptr, HH, nullptr, nullptr, 0.f);

    // 3. shared down -> out (plain store, overwrites poison)
    hgemm<false, 0><<<dim3(HH / 128, TT / 128, 1), 256, SMEM_BYTES>>>(
        p_hsa, 0, SSI,
        p_sdn, 0, HH,
        out, HH,
        nullptr, 0, 0,
        TT, nullptr, SSI, nullptr, nullptr, 0.f);

    // 4. routed gate_up (gather rows, interleaved N=2I) -> fused silu -> g_ha
    hgemm<true, 1><<<dim3((2 * II) / 128, TT / 128, EE), 256, SMEM_BYTES>>>(
        p_hs, 0, HH,
        p_wgu, (size_t)HH * 2 * II, 2 * II,
        nullptr, 0,
        p_ha, (size_t)TT * II, II,
        0, p_cnt, HH, p_tok, nullptr, 0.f);

    // 5. routed down + weighted scatter-add -> out
    hgemm<false, 2><<<dim3(HH / 128, TT / 128, EE), 256, SMEM_BYTES>>>(
        p_ha, (size_t)TT * II, II,
        p_wdn, (size_t)II * HH, HH,
        out, HH,
        nullptr, 0, 0,
        0, p_cnt, II, p_tok, p_cw, RSCALE);
}